// round 1
// baseline (speedup 1.0000x reference)
#include <cuda_runtime.h>

#define NODES   50000
#define EDGES   800000
#define FDIM    128
#define NGRAPH  128
#define NCLASS  10
#define NLAYERS 8

// ---------------- scratch (static device globals; no allocation) ----------------
__device__ float g_A[NODES * FDIM];   // current node features (ping target)
__device__ float g_T[NODES * FDIM];   // h @ W_rel   (messages)
__device__ float g_R[NODES * FDIM];   // h @ W_root + b
__device__ int   g_counts[NODES];
__device__ int   g_offsets[NODES];
__device__ int   g_fill[NODES];
__device__ int   g_csr[EDGES];
__device__ float g_pool[NGRAPH * FDIM];
__device__ float g_gcnt[NGRAPH];

// ---------------- CSR build ----------------
__global__ void hist_k(const int* __restrict__ dst, int E) {
    int i = blockIdx.x * blockDim.x + threadIdx.x;
    if (i < E) atomicAdd(&g_counts[dst[i]], 1);
}

// single-block exclusive scan of g_counts -> g_offsets (n up to ~50k)
__global__ void scan_k(int n) {
    __shared__ int warp_sums[32];
    __shared__ int s_carry;
    if (threadIdx.x == 0) s_carry = 0;
    __syncthreads();
    int lane = threadIdx.x & 31;
    int wid  = threadIdx.x >> 5;
    for (int base = 0; base < n; base += 1024) {
        int i = base + threadIdx.x;
        int v = (i < n) ? g_counts[i] : 0;
        int x = v;
        #pragma unroll
        for (int o = 1; o < 32; o <<= 1) {
            int y = __shfl_up_sync(0xFFFFFFFFu, x, o);
            if (lane >= o) x += y;
        }
        if (lane == 31) warp_sums[wid] = x;
        __syncthreads();
        if (wid == 0) {
            int s = warp_sums[lane];
            #pragma unroll
            for (int o = 1; o < 32; o <<= 1) {
                int y = __shfl_up_sync(0xFFFFFFFFu, s, o);
                if (lane >= o) s += y;
            }
            warp_sums[lane] = s;
        }
        __syncthreads();
        int block_excl = (wid > 0) ? warp_sums[wid - 1] : 0;
        int incl = x + block_excl;
        if (i < n) g_offsets[i] = s_carry + incl - v;
        __syncthreads();
        if (threadIdx.x == 1023) s_carry += warp_sums[31];
        __syncthreads();
    }
}

__global__ void fill_k(const int* __restrict__ src, const int* __restrict__ dst, int E) {
    int i = blockIdx.x * blockDim.x + threadIdx.x;
    if (i < E) {
        int d = dst[i];
        int pos = g_offsets[d] + atomicAdd(&g_fill[d], 1);
        g_csr[pos] = src[i];
    }
}

// ---------------- fused dual GEMM: T = A@Wr ; R = A@Ws + b ----------------
// C tile per block: 64 rows x 128 cols (full width), 256 threads,
// each thread 4x8 outputs per matrix.
#define BM 64
#define BK 16

__global__ __launch_bounds__(256, 2) void dual_gemm_k(
    const float* __restrict__ A, const float* __restrict__ Wr,
    const float* __restrict__ Ws, const float* __restrict__ bias,
    float* __restrict__ T, float* __restrict__ R, int N)
{
    __shared__ float As[BK][BM + 4];
    __shared__ float Brs[BK][FDIM];
    __shared__ float Bss[BK][FDIM];

    const int tid = threadIdx.x;
    const int tx = tid & 15;        // col group: tx*8
    const int ty = tid >> 4;        // row group: ty*4
    const int block_row = blockIdx.x * BM;

    float accT[4][8];
    float accR[4][8];
    #pragma unroll
    for (int i = 0; i < 4; i++)
        #pragma unroll
        for (int j = 0; j < 8; j++) { accT[i][j] = 0.f; accR[i][j] = 0.f; }

    const int ar = tid >> 2;            // 0..63 row within tile
    const int kq = (tid & 3) * 4;       // 0,4,8,12

    for (int k0 = 0; k0 < FDIM; k0 += BK) {
        // A tile (64 x 16), transposed into smem
        int grow = block_row + ar;
        float4 av = make_float4(0.f, 0.f, 0.f, 0.f);
        if (grow < N) av = *(const float4*)&A[grow * FDIM + k0 + kq];
        As[kq + 0][ar] = av.x;
        As[kq + 1][ar] = av.y;
        As[kq + 2][ar] = av.z;
        As[kq + 3][ar] = av.w;
        // W tiles (16 x 128) x 2 matrices
        #pragma unroll
        for (int r = 0; r < 2; r++) {
            int idx = tid + r * 256;        // 0..511 float4 index
            int wk = idx >> 5;              // 0..15
            int wc = (idx & 31) * 4;        // 0..124
            *(float4*)&Brs[wk][wc] = *(const float4*)&Wr[(k0 + wk) * FDIM + wc];
            *(float4*)&Bss[wk][wc] = *(const float4*)&Ws[(k0 + wk) * FDIM + wc];
        }
        __syncthreads();

        #pragma unroll
        for (int k = 0; k < BK; k++) {
            float4 a  = *(float4*)&As[k][ty * 4];
            float4 b0 = *(float4*)&Brs[k][tx * 8];
            float4 b1 = *(float4*)&Brs[k][tx * 8 + 4];
            float4 c0 = *(float4*)&Bss[k][tx * 8];
            float4 c1 = *(float4*)&Bss[k][tx * 8 + 4];
            float av4[4] = {a.x, a.y, a.z, a.w};
            float br[8] = {b0.x, b0.y, b0.z, b0.w, b1.x, b1.y, b1.z, b1.w};
            float bs[8] = {c0.x, c0.y, c0.z, c0.w, c1.x, c1.y, c1.z, c1.w};
            #pragma unroll
            for (int j = 0; j < 8; j++) {
                #pragma unroll
                for (int i = 0; i < 4; i++) {
                    accT[i][j] += av4[i] * br[j];
                    accR[i][j] += av4[i] * bs[j];
                }
            }
        }
        __syncthreads();
    }

    float bias_r[8];
    #pragma unroll
    for (int j = 0; j < 8; j++) bias_r[j] = bias[tx * 8 + j];

    #pragma unroll
    for (int i = 0; i < 4; i++) {
        int row = block_row + ty * 4 + i;
        if (row < N) {
            float4 t0 = make_float4(accT[i][0], accT[i][1], accT[i][2], accT[i][3]);
            float4 t1 = make_float4(accT[i][4], accT[i][5], accT[i][6], accT[i][7]);
            float4 r0 = make_float4(accR[i][0] + bias_r[0], accR[i][1] + bias_r[1],
                                    accR[i][2] + bias_r[2], accR[i][3] + bias_r[3]);
            float4 r1 = make_float4(accR[i][4] + bias_r[4], accR[i][5] + bias_r[5],
                                    accR[i][6] + bias_r[6], accR[i][7] + bias_r[7]);
            *(float4*)&T[row * FDIM + tx * 8]     = t0;
            *(float4*)&T[row * FDIM + tx * 8 + 4] = t1;
            *(float4*)&R[row * FDIM + tx * 8]     = r0;
            *(float4*)&R[row * FDIM + tx * 8 + 4] = r1;
        }
    }
}

// ---------------- aggregation: A[i] = maybe_relu(R[i] + sum_{e in CSR[i]} T[src_e]) ----
__global__ void agg_k(int do_relu) {
    int i = blockIdx.x;
    int t = threadIdx.x;
    float acc = g_R[i * FDIM + t];
    int beg = g_offsets[i];
    int end = beg + g_counts[i];
    int e = beg;
    for (; e + 4 <= end; e += 4) {
        int s0 = g_csr[e], s1 = g_csr[e + 1], s2 = g_csr[e + 2], s3 = g_csr[e + 3];
        float v0 = g_T[s0 * FDIM + t];
        float v1 = g_T[s1 * FDIM + t];
        float v2 = g_T[s2 * FDIM + t];
        float v3 = g_T[s3 * FDIM + t];
        acc += v0 + v1 + v2 + v3;
    }
    for (; e < end; e++) acc += g_T[g_csr[e] * FDIM + t];
    if (do_relu) acc = fmaxf(acc, 0.f);
    g_A[i * FDIM + t] = acc;
}

// ---------------- global mean pool (atomic) ----------------
__global__ void pool_k(const int* __restrict__ batch) {
    int i = blockIdx.x;
    int t = threadIdx.x;
    int g = batch[i];
    atomicAdd(&g_pool[g * FDIM + t], g_A[i * FDIM + t]);
    if (t == 0) atomicAdd(&g_gcnt[g], 1.f);
}

// ---------------- head: out[g] = (pool[g]/cnt[g]) @ Wlin + blin ----------------
__global__ void head_k(const float* __restrict__ Wlin, const float* __restrict__ blin,
                       float* __restrict__ out) {
    __shared__ float sh[FDIM];
    int g = blockIdx.x;
    int t = threadIdx.x;
    float c = fmaxf(g_gcnt[g], 1.f);
    sh[t] = g_pool[g * FDIM + t] / c;
    __syncthreads();
    if (t < NCLASS) {
        float s = blin[t];
        #pragma unroll 8
        for (int k = 0; k < FDIM; k++) s += sh[k] * Wlin[k * NCLASS + t];
        out[g * NCLASS + t] = s;
    }
}

// ---------------- launch ----------------
extern "C" void kernel_launch(void* const* d_in, const int* in_sizes, int n_in,
                              void* d_out, int out_size) {
    const float* x     = (const float*)d_in[0];
    const int*   ei    = (const int*)d_in[1];
    const int*   batch = (const int*)d_in[2];
    const float* Wrel  = (const float*)d_in[3];
    const float* Wroot = (const float*)d_in[4];
    const float* b     = (const float*)d_in[5];
    const float* Wlin  = (const float*)d_in[6];
    const float* blin  = (const float*)d_in[7];
    float* out = (float*)d_out;

    const int N = in_sizes[0] / FDIM;
    const int E = in_sizes[1] / 2;
    const int* src = ei;
    const int* dst = ei + E;

    void *pCounts, *pFill, *pPool, *pGcnt, *pA, *pT, *pR;
    cudaGetSymbolAddress(&pCounts, g_counts);
    cudaGetSymbolAddress(&pFill,   g_fill);
    cudaGetSymbolAddress(&pPool,   g_pool);
    cudaGetSymbolAddress(&pGcnt,   g_gcnt);
    cudaGetSymbolAddress(&pA,      g_A);
    cudaGetSymbolAddress(&pT,      g_T);
    cudaGetSymbolAddress(&pR,      g_R);

    cudaMemsetAsync(pCounts, 0, N * sizeof(int));
    cudaMemsetAsync(pFill,   0, N * sizeof(int));
    cudaMemsetAsync(pPool,   0, NGRAPH * FDIM * sizeof(float));
    cudaMemsetAsync(pGcnt,   0, NGRAPH * sizeof(float));

    hist_k<<<(E + 255) / 256, 256>>>(dst, E);
    scan_k<<<1, 1024>>>(N);
    fill_k<<<(E + 255) / 256, 256>>>(src, dst, E);

    int gemm_grid = (N + BM - 1) / BM;
    for (int l = 0; l < NLAYERS; l++) {
        const float* hin = (l == 0) ? x : (const float*)pA;
        dual_gemm_k<<<gemm_grid, 256>>>(hin,
                                        Wrel  + (size_t)l * FDIM * FDIM,
                                        Wroot + (size_t)l * FDIM * FDIM,
                                        b + (size_t)l * FDIM,
                                        (float*)pT, (float*)pR, N);
        agg_k<<<N, FDIM>>>(l < NLAYERS - 1 ? 1 : 0);
    }

    pool_k<<<N, FDIM>>>(batch);
    head_k<<<NGRAPH, FDIM>>>(Wlin, blin, out);
}

// round 5
// speedup vs baseline: 1.5178x; 1.5178x over previous
#include <cuda_runtime.h>
#include <cuda_bf16.h>
#include <stdint.h>

#define NODES   50000
#define EDGES   800000
#define FDIM    128
#define NGRAPH  128
#define NCLASS  10
#define NLAYERS 8
#define TILE_M  128

// smem tile: 128 rows x 128 bf16, row stride 136 bf16 (272B) for conflict-free ldmatrix
#define TROW    272
#define TSZ     (128 * TROW)          // 34816 bytes
#define OFF_AH  0
#define OFF_AL  (1 * TSZ)
#define OFF_W0  (2 * TSZ)             // W hi (phase-dependent)
#define OFF_W1  (3 * TSZ)             // W lo (phase-dependent)
#define SMEM_TOTAL (4 * TSZ)          // 139264

// ---------------- scratch ----------------
__device__ float         g_A[NODES * FDIM];
__device__ __nv_bfloat16 g_Ah[NODES * FDIM];
__device__ __nv_bfloat16 g_Al[NODES * FDIM];
__device__ float         g_T[NODES * FDIM];
__device__ float         g_R[NODES * FDIM];
__device__ __nv_bfloat16 g_Wb[NLAYERS][4][FDIM * FDIM];  // 0=Wr_hi 1=Wr_lo 2=Ws_hi 3=Ws_lo, [n][k]
__device__ int   g_counts[NODES];
__device__ int   g_offsets[NODES];
__device__ int   g_fill[NODES];
__device__ int   g_csr[EDGES];
__device__ float g_pool[NGRAPH * FDIM];
__device__ float g_gcnt[NGRAPH];

// ---------------- helpers ----------------
static __device__ __forceinline__ uint32_t smem_u32(const void* p) {
    uint32_t a;
    asm("{ .reg .u64 t; cvta.to.shared.u64 t, %1; cvt.u32.u64 %0, t; }" : "=r"(a) : "l"(p));
    return a;
}
static __device__ __forceinline__ void ldsm4(uint32_t& r0, uint32_t& r1, uint32_t& r2,
                                             uint32_t& r3, uint32_t addr) {
    asm volatile("ldmatrix.sync.aligned.m8n8.x4.shared.b16 {%0,%1,%2,%3}, [%4];"
                 : "=r"(r0), "=r"(r1), "=r"(r2), "=r"(r3) : "r"(addr));
}
static __device__ __forceinline__ void mma16816(float* c, uint32_t a0, uint32_t a1,
                                                uint32_t a2, uint32_t a3,
                                                uint32_t b0, uint32_t b1) {
    asm volatile(
        "mma.sync.aligned.m16n8k16.row.col.f32.bf16.bf16.f32 "
        "{%0,%1,%2,%3}, {%4,%5,%6,%7}, {%8,%9}, {%0,%1,%2,%3};"
        : "+f"(c[0]), "+f"(c[1]), "+f"(c[2]), "+f"(c[3])
        : "r"(a0), "r"(a1), "r"(a2), "r"(a3), "r"(b0), "r"(b1));
}

// ---------------- CSR build ----------------
__global__ void hist_k(const int* __restrict__ dst, int E) {
    int i = blockIdx.x * blockDim.x + threadIdx.x;
    if (i < E) atomicAdd(&g_counts[dst[i]], 1);
}

__global__ void scan_k(int n) {
    __shared__ int warp_sums[32];
    __shared__ int s_carry;
    if (threadIdx.x == 0) s_carry = 0;
    __syncthreads();
    int lane = threadIdx.x & 31;
    int wid  = threadIdx.x >> 5;
    for (int base = 0; base < n; base += 1024) {
        int i = base + threadIdx.x;
        int v = (i < n) ? g_counts[i] : 0;
        int x = v;
        #pragma unroll
        for (int o = 1; o < 32; o <<= 1) {
            int y = __shfl_up_sync(0xFFFFFFFFu, x, o);
            if (lane >= o) x += y;
        }
        if (lane == 31) warp_sums[wid] = x;
        __syncthreads();
        if (wid == 0) {
            int s = warp_sums[lane];
            #pragma unroll
            for (int o = 1; o < 32; o <<= 1) {
                int y = __shfl_up_sync(0xFFFFFFFFu, s, o);
                if (lane >= o) s += y;
            }
            warp_sums[lane] = s;
        }
        __syncthreads();
        int block_excl = (wid > 0) ? warp_sums[wid - 1] : 0;
        int incl = x + block_excl;
        if (i < n) g_offsets[i] = s_carry + incl - v;
        __syncthreads();
        if (threadIdx.x == 1023) s_carry += warp_sums[31];
        __syncthreads();
    }
}

__global__ void fill_k(const int* __restrict__ src, const int* __restrict__ dst, int E) {
    int i = blockIdx.x * blockDim.x + threadIdx.x;
    if (i < E) {
        int d = dst[i];
        int pos = g_offsets[d] + atomicAdd(&g_fill[d], 1);
        g_csr[pos] = src[i];
    }
}

// ---------------- weight prep: split + transpose to [n][k] bf16 hi/lo ----------------
__global__ void prep_w_k(const float* __restrict__ Wrel, const float* __restrict__ Wroot) {
    int idx = blockIdx.x * blockDim.x + threadIdx.x;
    if (idx >= NLAYERS * FDIM * FDIM) return;
    int l = idx >> 14;
    int r = idx & 16383;
    int k = r >> 7;
    int n = r & 127;
    float wr = Wrel[idx];    // idx == l*16384 + k*128 + n
    float ws = Wroot[idx];
    __nv_bfloat16 h;
    h = __float2bfloat16(wr);
    g_Wb[l][0][n * 128 + k] = h;
    g_Wb[l][1][n * 128 + k] = __float2bfloat16(wr - __bfloat162float(h));
    h = __float2bfloat16(ws);
    g_Wb[l][2][n * 128 + k] = h;
    g_Wb[l][3][n * 128 + k] = __float2bfloat16(ws - __bfloat162float(h));
}

// ---------------- x -> bf16 hi/lo ----------------
__global__ void conv_x_k(const float* __restrict__ x, int total) {
    int i = blockIdx.x * blockDim.x + threadIdx.x;
    if (i < total) {
        float v = x[i];
        __nv_bfloat16 h = __float2bfloat16(v);
        g_Ah[i] = h;
        g_Al[i] = __float2bfloat16(v - __bfloat162float(h));
    }
}

// ---------------- mma.sync dual GEMM: T = A@Wr ; R = A@Ws + b (split-bf16 x3) -------
// block: 128 rows x 128 cols per phase (phase 0 -> T, phase 1 -> R).
// 512 thr, 16 warps, warp tile 32x32.
__global__ __launch_bounds__(512, 1)
void mma_gemm_k(int layer, const float* __restrict__ bias, int N)
{
    extern __shared__ __align__(1024) char smem[];
    const uint32_t sb = smem_u32(smem);
    const int tid = threadIdx.x;
    const int wid = tid >> 5;
    const int lane = tid & 31;
    const int mw = wid >> 2;            // 0..3: warp row group (32 rows)
    const int nw = wid & 3;             // 0..3: warp col group (32 cols)
    const int row0 = blockIdx.x * TILE_M;
    const int nrows = min(TILE_M, N - row0);

    // ---- load A hi/lo tiles into smem (once) ----
    {
        const __nv_bfloat16* srcs[2] = { g_Ah + (size_t)row0 * FDIM,
                                         g_Al + (size_t)row0 * FDIM };
        const int off[2] = { OFF_AH, OFF_AL };
        #pragma unroll
        for (int a = 0; a < 2; a++) {
            #pragma unroll
            for (int it = 0; it < 4; it++) {
                int idx = tid + it * 512;           // 0..2047 uint4
                int r = idx >> 4;
                int c = (idx & 15) * 8;             // bf16 col
                uint4 v = make_uint4(0, 0, 0, 0);
                if (r < nrows) v = *(const uint4*)(srcs[a] + (size_t)r * FDIM + c);
                *(uint4*)(smem + off[a] + r * TROW + c * 2) = v;
            }
        }
    }

    // ---- per-lane ldmatrix base addresses ----
    // A frag (m16k16 x4): row (lane&7) + ((lane>>3)&1)*8, col (lane>>4)*8
    const int aRow = (lane & 7) + ((lane >> 3) & 1) * 8;
    const int aCol = (lane >> 4) * 8;
    const uint32_t aLane = sb + (uint32_t)((mw * 32 + aRow) * TROW + aCol * 2);
    // B frag (n16k16 x4): n (lane&7) + ((lane>>4)&1)*8, col ((lane>>3)&1)*8
    const int bRow = ((lane >> 4) & 1) * 8 + (lane & 7);
    const int bCol = ((lane >> 3) & 1) * 8;
    const uint32_t bLane = sb + (uint32_t)((nw * 32 + bRow) * TROW + bCol * 2);

    const int g = lane >> 2;
    const int t = lane & 3;

    #pragma unroll
    for (int phase = 0; phase < 2; phase++) {
        // ---- load W hi/lo tiles for this phase ----
        {
            const __nv_bfloat16* srcH = &g_Wb[layer][phase * 2 + 0][0];
            const __nv_bfloat16* srcL = &g_Wb[layer][phase * 2 + 1][0];
            #pragma unroll
            for (int it = 0; it < 4; it++) {
                int idx = tid + it * 512;
                int r = idx >> 4;
                int c = (idx & 15) * 8;
                *(uint4*)(smem + OFF_W0 + r * TROW + c * 2) =
                    *(const uint4*)(srcH + (size_t)r * FDIM + c);
                *(uint4*)(smem + OFF_W1 + r * TROW + c * 2) =
                    *(const uint4*)(srcL + (size_t)r * FDIM + c);
            }
        }
        __syncthreads();

        float acc[2][4][4];
        #pragma unroll
        for (int mt = 0; mt < 2; mt++)
            #pragma unroll
            for (int nt = 0; nt < 4; nt++)
                #pragma unroll
                for (int q = 0; q < 4; q++) acc[mt][nt][q] = 0.f;

        const int segA[3] = { OFF_AH, OFF_AH, OFF_AL };
        const int segW[3] = { OFF_W0, OFF_W1, OFF_W0 };
        #pragma unroll
        for (int s = 0; s < 3; s++) {
            uint32_t aBase = aLane + segA[s];
            uint32_t bBase = bLane + segW[s];
            #pragma unroll
            for (int j = 0; j < 8; j++) {
                uint32_t a[2][4];
                #pragma unroll
                for (int mt = 0; mt < 2; mt++)
                    ldsm4(a[mt][0], a[mt][1], a[mt][2], a[mt][3],
                          aBase + (uint32_t)(mt * 16 * TROW + j * 32));
                uint32_t b[2][4];  // [pair of n16][b0_n0, b1_n0, b0_n1, b1_n1]
                #pragma unroll
                for (int p = 0; p < 2; p++)
                    ldsm4(b[p][0], b[p][1], b[p][2], b[p][3],
                          bBase + (uint32_t)(p * 16 * TROW + j * 32));
                #pragma unroll
                for (int mt = 0; mt < 2; mt++)
                    #pragma unroll
                    for (int p = 0; p < 2; p++) {
                        mma16816(acc[mt][p * 2 + 0], a[mt][0], a[mt][1], a[mt][2], a[mt][3],
                                 b[p][0], b[p][1]);
                        mma16816(acc[mt][p * 2 + 1], a[mt][0], a[mt][1], a[mt][2], a[mt][3],
                                 b[p][2], b[p][3]);
                    }
            }
        }

        // ---- epilogue for this phase ----
        float* dmat = (phase == 0) ? g_T : g_R;
        #pragma unroll
        for (int mt = 0; mt < 2; mt++) {
            int r0 = row0 + mw * 32 + mt * 16 + g;
            int r1 = r0 + 8;
            #pragma unroll
            for (int nt = 0; nt < 4; nt++) {
                int c = nw * 32 + nt * 8 + t * 2;
                float b0 = 0.f, b1 = 0.f;
                if (phase == 1) { b0 = bias[c]; b1 = bias[c + 1]; }
                if (r0 < N) {
                    float2 v = make_float2(acc[mt][nt][0] + b0, acc[mt][nt][1] + b1);
                    *(float2*)(dmat + (size_t)r0 * FDIM + c) = v;
                }
                if (r1 < N) {
                    float2 v = make_float2(acc[mt][nt][2] + b0, acc[mt][nt][3] + b1);
                    *(float2*)(dmat + (size_t)r1 * FDIM + c) = v;
                }
            }
        }
        if (phase == 0) __syncthreads();   // all warps done with Wr tiles before overwrite
    }
}

// ---------------- aggregation + relu + bf16 split (fused) ----------------
__global__ void agg_k(int do_relu, int last) {
    int i = blockIdx.x;
    int t = threadIdx.x;
    float acc = g_R[i * FDIM + t];
    int beg = g_offsets[i];
    int end = beg + g_counts[i];
    int e = beg;
    for (; e + 4 <= end; e += 4) {
        int s0 = g_csr[e], s1 = g_csr[e + 1], s2 = g_csr[e + 2], s3 = g_csr[e + 3];
        float v0 = g_T[s0 * FDIM + t];
        float v1 = g_T[s1 * FDIM + t];
        float v2 = g_T[s2 * FDIM + t];
        float v3 = g_T[s3 * FDIM + t];
        acc += v0 + v1 + v2 + v3;
    }
    for (; e < end; e++) acc += g_T[g_csr[e] * FDIM + t];
    if (do_relu) acc = fmaxf(acc, 0.f);
    if (last) {
        g_A[i * FDIM + t] = acc;
    } else {
        __nv_bfloat16 h = __float2bfloat16(acc);
        g_Ah[i * FDIM + t] = h;
        g_Al[i * FDIM + t] = __float2bfloat16(acc - __bfloat162float(h));
    }
}

// ---------------- global mean pool ----------------
__global__ void pool_k(const int* __restrict__ batch) {
    int i = blockIdx.x;
    int t = threadIdx.x;
    int g = batch[i];
    atomicAdd(&g_pool[g * FDIM + t], g_A[i * FDIM + t]);
    if (t == 0) atomicAdd(&g_gcnt[g], 1.f);
}

// ---------------- head ----------------
__global__ void head_k(const float* __restrict__ Wlin, const float* __restrict__ blin,
                       float* __restrict__ out) {
    __shared__ float sh[FDIM];
    int g = blockIdx.x;
    int t = threadIdx.x;
    float c = fmaxf(g_gcnt[g], 1.f);
    sh[t] = g_pool[g * FDIM + t] / c;
    __syncthreads();
    if (t < NCLASS) {
        float s = blin[t];
        #pragma unroll 8
        for (int k = 0; k < FDIM; k++) s += sh[k] * Wlin[k * NCLASS + t];
        out[g * NCLASS + t] = s;
    }
}

// ---------------- launch ----------------
extern "C" void kernel_launch(void* const* d_in, const int* in_sizes, int n_in,
                              void* d_out, int out_size) {
    const float* x     = (const float*)d_in[0];
    const int*   ei    = (const int*)d_in[1];
    const int*   batch = (const int*)d_in[2];
    const float* Wrel  = (const float*)d_in[3];
    const float* Wroot = (const float*)d_in[4];
    const float* b     = (const float*)d_in[5];
    const float* Wlin  = (const float*)d_in[6];
    const float* blin  = (const float*)d_in[7];
    float* out = (float*)d_out;

    const int N = in_sizes[0] / FDIM;
    const int E = in_sizes[1] / 2;
    const int* src = ei;
    const int* dst = ei + E;

    void *pCounts, *pFill, *pPool, *pGcnt;
    cudaGetSymbolAddress(&pCounts, g_counts);
    cudaGetSymbolAddress(&pFill,   g_fill);
    cudaGetSymbolAddress(&pPool,   g_pool);
    cudaGetSymbolAddress(&pGcnt,   g_gcnt);

    cudaMemsetAsync(pCounts, 0, N * sizeof(int));
    cudaMemsetAsync(pFill,   0, N * sizeof(int));
    cudaMemsetAsync(pPool,   0, NGRAPH * FDIM * sizeof(float));
    cudaMemsetAsync(pGcnt,   0, NGRAPH * sizeof(float));

    cudaFuncSetAttribute(mma_gemm_k, cudaFuncAttributeMaxDynamicSharedMemorySize, SMEM_TOTAL);

    prep_w_k<<<(NLAYERS * FDIM * FDIM + 255) / 256, 256>>>(Wrel, Wroot);
    conv_x_k<<<(N * FDIM + 255) / 256, 256>>>(x, N * FDIM);

    hist_k<<<(E + 255) / 256, 256>>>(dst, E);
    scan_k<<<1, 1024>>>(N);
    fill_k<<<(E + 255) / 256, 256>>>(src, dst, E);

    int tiles = (N + TILE_M - 1) / TILE_M;
    for (int l = 0; l < NLAYERS; l++) {
        mma_gemm_k<<<tiles, 512, SMEM_TOTAL>>>(l, b + (size_t)l * FDIM, N);
        agg_k<<<N, FDIM>>>(l < NLAYERS - 1 ? 1 : 0, l == NLAYERS - 1 ? 1 : 0);
    }

    pool_k<<<N, FDIM>>>(batch);
    head_k<<<NGRAPH, FDIM>>>(Wlin, blin, out);
}